// round 15
// baseline (speedup 1.0000x reference)
#include <cuda_runtime.h>
#include <cuda_bf16.h>
#include <cstdint>

// S4D forward, exact diagonal-SSM recurrence, chunked over L (4 x 512):
//   a[d,n]  = exp(dt_d * A_n),  A_n = -0.5*(n+1)
//   cb[d,n] = C[d,n]*B[d,n]*expm1(dt_d*A_n)/A_n
//   h_n[l]  = a_n*h_n[l-1] + x[l],   y[l] = sum_n cb_n*h_n[l] + D_d*x[l]
//
// R15: K3 = R11 body (measured 118us, three-run stable). K1 split over TIME:
// each 512-chunk's boundary state factors as S = a^256*Sh0 + Sh1 with the two
// half-states computed from zero over independent 256-step ranges -> 3072
// warp-CTAs at exactly half the per-CTA work (compute AND staging). K3
// prologue recombines halves: S_cp = a^256 (.) Sh[2cp] + Sh[2cp+1].

#define BATCH   8
#define LEN     2048
#define DMODEL  1024
#define NSTATE  64

#define NCHUNK  4
#define TCH     512    // chunk length
#define HCH     256    // half-chunk (K1 unit)

#define TILE    64     // staged steps per tile
#define NTILES3 (TCH / TILE)   // K3: 8
#define NTILES1 (HCH / TILE)   // K1: 4

#define K1_DT   16     // K1 channels per warp-CTA
#define K3_DT   8      // K3 channels per warp-CTA

typedef unsigned long long u64;
typedef unsigned int       u32;

// half-chunk boundary states: [halfchunk 0..5][b][d][n]
// halfchunk index = 2*ck + half, for ck = 0..NCHUNK-2
__device__ float S_scratch[2 * (NCHUNK - 1) * BATCH * DMODEL * NSTATE];

__device__ __forceinline__ u64 pack2(float lo, float hi) {
    u64 r; asm("mov.b64 %0, {%1,%2};" : "=l"(r) : "f"(lo), "f"(hi)); return r;
}
__device__ __forceinline__ void unpack2(u64 v, float& lo, float& hi) {
    asm("mov.b64 {%0,%1}, %2;" : "=f"(lo), "=f"(hi) : "l"(v));
}
__device__ __forceinline__ u64 fma2(u64 a, u64 b, u64 c) {
    u64 d; asm("fma.rn.f32x2 %0, %1, %2, %3;" : "=l"(d) : "l"(a), "l"(b), "l"(c)); return d;
}
__device__ __forceinline__ u64 mul2(u64 a, u64 b) {
    u64 d; asm("mul.rn.f32x2 %0, %1, %2;" : "=l"(d) : "l"(a), "l"(b)); return d;
}
__device__ __forceinline__ u64 add2(u64 a, u64 b) {
    u64 d; asm("add.rn.f32x2 %0, %1, %2;" : "=l"(d) : "l"(a), "l"(b)); return d;
}
__device__ __forceinline__ void cp_async16(u32 smem_dst, const void* gmem_src) {
    asm volatile("cp.async.cg.shared.global [%0], [%1], 16;" :: "r"(smem_dst), "l"(gmem_src));
}
__device__ __forceinline__ u32 smem_u32(const void* p) {
    return (u32)__cvta_generic_to_shared(p);
}

// ---------------- K1: half-chunk boundary states ----------------------------
// grid.x = (DMODEL/K1_DT) * 2 : bit0 of blockIdx.x selects the half.
__global__ __launch_bounds__(32)
void s4d_k1_states(const float* __restrict__ x,
                   const float* __restrict__ log_dt)
{
    __shared__ float XS[2][TILE * K1_DT];   // 8 KB

    const int lane = threadIdx.x;
    const int c    = lane & 15;           // channel within tile
    const int half = lane >> 4;           // state half (0..1)
    const int hx   = blockIdx.x & 1;      // time half (0..1)
    const int d0   = (blockIdx.x >> 1) * K1_DT;
    const int d    = d0 + c;
    const int b    = blockIdx.y;
    const int ck   = blockIdx.z;          // 0..NCHUNK-2

    u64 a2[16], s2[16];
    {
        const float dt = expf(log_dt[d]);
        #pragma unroll
        for (int i = 0; i < 16; i++) {
            const int n0 = half * 32 + 2 * i;
            a2[i] = pack2(expf(dt * (-0.5f * (float)(n0 + 1))),
                          expf(dt * (-0.5f * (float)(n0 + 2))));
            s2[i] = 0ull;
        }
    }

    const float* xg = x + ((size_t)b * LEN + (size_t)ck * TCH + (size_t)hx * HCH) * DMODEL + d0;

    // stage: 64 rows x 64B; lane -> row = lane>>2 (8 rows/pass), 16B quarter
    const int rq = lane >> 2;
    const int cq = (lane & 3) * 4;

    #pragma unroll
    for (int rr = 0; rr < TILE; rr += 8)
        cp_async16(smem_u32(&XS[0][(rr + rq) * K1_DT + cq]),
                   xg + (size_t)(rr + rq) * DMODEL + cq);
    asm volatile("cp.async.commit_group;");

    #pragma unroll 1
    for (int t = 0; t < NTILES1; t++) {
        const int buf = t & 1;
        if (t + 1 < NTILES1) {
            const float* src = xg + (size_t)(t + 1) * TILE * DMODEL;
            #pragma unroll
            for (int rr = 0; rr < TILE; rr += 8)
                cp_async16(smem_u32(&XS[buf ^ 1][(rr + rq) * K1_DT + cq]),
                           src + (size_t)(rr + rq) * DMODEL + cq);
            asm volatile("cp.async.commit_group;");
            asm volatile("cp.async.wait_group 1;");
        } else {
            asm volatile("cp.async.wait_group 0;");
        }
        __syncwarp();

        const float* xs = &XS[buf][c];
        #pragma unroll 1
        for (int r0 = 0; r0 < TILE; r0 += 8) {
            #pragma unroll
            for (int r = 0; r < 8; r++) {
                const float xv = xs[(r0 + r) * K1_DT];
                const u64   xx = pack2(xv, xv);
                #pragma unroll
                for (int i = 0; i < 16; i++)
                    s2[i] = fma2(a2[i], s2[i], xx);
            }
        }
        __syncwarp();
    }

    const int hidx = 2 * ck + hx;
    u64* Sp = (u64*)(S_scratch + ((((size_t)hidx * BATCH + b) * DMODEL + d) * NSTATE + half * 32));
    #pragma unroll
    for (int i = 0; i < 16; i++) Sp[i] = s2[i];
}

// ---------------- K3: lean 8-channel warp-CTA, staged x (R11 body) ----------
__global__ __launch_bounds__(32)
void s4d_k3_main(const float* __restrict__ x,
                 const float* __restrict__ log_dt,
                 const float* __restrict__ Bm,
                 const float* __restrict__ Cm,
                 const float* __restrict__ Dv,
                 float* __restrict__ y)
{
    __shared__ float XS[2][TILE * K3_DT];   // 4 KB

    const int lane = threadIdx.x;
    const int c    = lane & 7;            // channel within tile
    const int g    = lane >> 3;           // state quarter (0..3)
    const int d0   = blockIdx.x * K3_DT;
    const int d    = d0 + c;
    const int b    = blockIdx.y;
    const int ck   = blockIdx.z;          // 0..3

    // ---- 16 states per lane: n = g*16 + 0..15 (8 packed pairs) ----
    u64 a2[8], cb2[8], s2[8];
    {
        const float dt = expf(log_dt[d]);
        #pragma unroll
        for (int i = 0; i < 8; i++) {
            const int   n0   = g * 16 + 2 * i;
            const float An0  = -0.5f * (float)(n0 + 1);
            const float An1  = -0.5f * (float)(n0 + 2);
            const float dtA0 = dt * An0;
            const float dtA1 = dt * An1;
            a2[i]  = pack2(expf(dtA0), expf(dtA1));
            cb2[i] = pack2(Cm[d * NSTATE + n0]     * Bm[d * NSTATE + n0]     * (expm1f(dtA0) / An0),
                           Cm[d * NSTATE + n0 + 1] * Bm[d * NSTATE + n0 + 1] * (expm1f(dtA1) / An1));

            // carry-in: S_cp = a^HCH (.) Sh[2cp] + Sh[2cp+1];
            // h0 = sum_{cp<ck} a^(TCH*(ck-1-cp)) (.) S_cp, built with
            // incremental powers f *= a^TCH (a^TCH = (a^HCH)^2).
            u64 h0 = 0ull;
            if (ck > 0) {
                const u64 aH = pack2(expf(dtA0 * (float)HCH), expf(dtA1 * (float)HCH));
                const u64 w2 = mul2(aH, aH);   // a^TCH
                u64 f2 = pack2(1.0f, 1.0f);
                #pragma unroll 1
                for (int cp = ck - 1; cp >= 0; cp--) {
                    const float* base = S_scratch +
                        ((((size_t)(2 * cp) * BATCH + b) * DMODEL + d) * NSTATE + g * 16 + 2 * i);
                    const u64 sv0 = *(const u64*)base;                                   // Sh[2cp]
                    const u64 sv1 = *(const u64*)(base + (size_t)BATCH * DMODEL * NSTATE); // Sh[2cp+1]
                    const u64 scp = fma2(aH, sv0, sv1);
                    h0 = fma2(f2, scp, h0);
                    f2 = mul2(f2, w2);
                }
            }
            s2[i] = h0;
        }
    }
    const float Dd = Dv[d];

    const float* xg = x + ((size_t)b * LEN + (size_t)ck * TCH) * DMODEL + d0;
    float*       yb = y + ((size_t)b * LEN + (size_t)ck * TCH) * DMODEL + d;

    // stage: 64 rows x 32B; lane -> row = lane>>1 (16 rows/pass), 16B half
    const int rq = lane >> 1;             // 0..15
    const int cq = (lane & 1) * 4;        // float offset 0 or 4

    #pragma unroll
    for (int rr = 0; rr < TILE; rr += 16)
        cp_async16(smem_u32(&XS[0][(rr + rq) * K3_DT + cq]),
                   xg + (size_t)(rr + rq) * DMODEL + cq);
    asm volatile("cp.async.commit_group;");

    #pragma unroll 1
    for (int t = 0; t < NTILES3; t++) {
        const int buf = t & 1;
        if (t + 1 < NTILES3) {
            const float* src = xg + (size_t)(t + 1) * TILE * DMODEL;
            #pragma unroll
            for (int rr = 0; rr < TILE; rr += 16)
                cp_async16(smem_u32(&XS[buf ^ 1][(rr + rq) * K3_DT + cq]),
                           src + (size_t)(rr + rq) * DMODEL + cq);
            asm volatile("cp.async.commit_group;");
            asm volatile("cp.async.wait_group 1;");
        } else {
            asm volatile("cp.async.wait_group 0;");
        }
        __syncwarp();

        const float* xs = &XS[buf][c];
        #pragma unroll 1
        for (int r0 = 0; r0 < TILE; r0 += 8) {
            #pragma unroll
            for (int r = 0; r < 8; r++) {
                const float xv = xs[(r0 + r) * K3_DT];   // broadcast across g
                const u64   xx = pack2(xv, xv);
                s2[0] = fma2(a2[0], s2[0], xx);
                s2[1] = fma2(a2[1], s2[1], xx);
                s2[2] = fma2(a2[2], s2[2], xx);
                s2[3] = fma2(a2[3], s2[3], xx);
                s2[4] = fma2(a2[4], s2[4], xx);
                s2[5] = fma2(a2[5], s2[5], xx);
                s2[6] = fma2(a2[6], s2[6], xx);
                s2[7] = fma2(a2[7], s2[7], xx);
                u64 acc0 = mul2(cb2[0], s2[0]);
                u64 acc1 = mul2(cb2[1], s2[1]);
                acc0 = fma2(cb2[2], s2[2], acc0);
                acc1 = fma2(cb2[3], s2[3], acc1);
                acc0 = fma2(cb2[4], s2[4], acc0);
                acc1 = fma2(cb2[5], s2[5], acc1);
                acc0 = fma2(cb2[6], s2[6], acc0);
                acc1 = fma2(cb2[7], s2[7], acc1);
                const u64 acc = add2(acc0, acc1);
                float lo, hi;
                unpack2(acc, lo, hi);
                float p = lo + hi;
                p += __shfl_xor_sync(0xffffffffu, p, 8);
                p += __shfl_xor_sync(0xffffffffu, p, 16);
                if (g == 0)
                    yb[(size_t)(t * TILE + r0 + r) * DMODEL] = fmaf(Dd, xv, p);
            }
        }
        __syncwarp();
    }
}

extern "C" void kernel_launch(void* const* d_in, const int* in_sizes, int n_in,
                              void* d_out, int out_size)
{
    const float* x      = (const float*)d_in[0];  // [8, 2048, 1024]
    const float* log_dt = (const float*)d_in[1];  // [1024]
    const float* Bm     = (const float*)d_in[2];  // [1024, 64]
    const float* Cm     = (const float*)d_in[3];  // [1024, 64]
    const float* Dv     = (const float*)d_in[4];  // [1024]
    float*       y      = (float*)d_out;          // [8, 2048, 1024]

    dim3 block(32);

    dim3 g1(2 * DMODEL / K1_DT, BATCH, NCHUNK - 1);  // (128, 8, 3) = 3072 warp-CTAs
    s4d_k1_states<<<g1, block>>>(x, log_dt);

    dim3 g3(DMODEL / K3_DT, BATCH, NCHUNK);          // (128, 8, 4) = 4096 warp-CTAs
    s4d_k3_main<<<g3, block>>>(x, log_dt, Bm, Cm, Dv, y);
}

// round 16
// speedup vs baseline: 1.0725x; 1.0725x over previous
#include <cuda_runtime.h>
#include <cuda_bf16.h>
#include <cstdint>

// S4D forward, exact diagonal-SSM recurrence, chunked over L (4 x 512):
//   a[d,n]  = exp(dt_d * A_n),  A_n = -0.5*(n+1)
//   cb[d,n] = C[d,n]*B[d,n]*expm1(dt_d*A_n)/A_n
//   h_n[l]  = a_n*h_n[l-1] + x[l],   y[l] = sum_n cb_n*h_n[l] + D_d*x[l]
//
// R16: R11 config (measured best 153.6us) with ONE change: K3's inner 8-step
// block defers the shuffle+store epilogue — all 8 per-lane partials are
// computed first (pure FMA), then the 8 independent 2-round shfl.xor chains
// are issued back-to-back (pipelined 26-cyc latency instead of exposed), then
// a store burst. K1 and everything else byte-identical to R11.

#define BATCH   8
#define LEN     2048
#define DMODEL  1024
#define NSTATE  64

#define NCHUNK  4
#define TCH     512    // chunk length

#define TILE    64     // staged steps per tile
#define NTILES  (TCH / TILE)

#define K1_DT   16     // K1 channels per warp-CTA
#define K3_DT   8      // K3 channels per warp-CTA

typedef unsigned long long u64;
typedef unsigned int       u32;

// chunk-final states: [chunk 0..2][b][d][n]
__device__ float S_scratch[(NCHUNK - 1) * BATCH * DMODEL * NSTATE];

__device__ __forceinline__ u64 pack2(float lo, float hi) {
    u64 r; asm("mov.b64 %0, {%1,%2};" : "=l"(r) : "f"(lo), "f"(hi)); return r;
}
__device__ __forceinline__ void unpack2(u64 v, float& lo, float& hi) {
    asm("mov.b64 {%0,%1}, %2;" : "=f"(lo), "=f"(hi) : "l"(v));
}
__device__ __forceinline__ u64 fma2(u64 a, u64 b, u64 c) {
    u64 d; asm("fma.rn.f32x2 %0, %1, %2, %3;" : "=l"(d) : "l"(a), "l"(b), "l"(c)); return d;
}
__device__ __forceinline__ u64 mul2(u64 a, u64 b) {
    u64 d; asm("mul.rn.f32x2 %0, %1, %2;" : "=l"(d) : "l"(a), "l"(b)); return d;
}
__device__ __forceinline__ u64 add2(u64 a, u64 b) {
    u64 d; asm("add.rn.f32x2 %0, %1, %2;" : "=l"(d) : "l"(a), "l"(b)); return d;
}
__device__ __forceinline__ void cp_async16(u32 smem_dst, const void* gmem_src) {
    asm volatile("cp.async.cg.shared.global [%0], [%1], 16;" :: "r"(smem_dst), "l"(gmem_src));
}
__device__ __forceinline__ u32 smem_u32(const void* p) {
    return (u32)__cvta_generic_to_shared(p);
}

// ---------------- K1: chunk-final states for chunks 0..2 (R11 body) ---------
__global__ __launch_bounds__(32)
void s4d_k1_states(const float* __restrict__ x,
                   const float* __restrict__ log_dt)
{
    __shared__ float XS[2][TILE * K1_DT];   // 8 KB

    const int lane = threadIdx.x;
    const int c    = lane & 15;           // channel within tile
    const int half = lane >> 4;           // state half (0..1)
    const int d0   = blockIdx.x * K1_DT;
    const int d    = d0 + c;
    const int b    = blockIdx.y;
    const int ck   = blockIdx.z;          // 0..2

    u64 a2[16], s2[16];
    {
        const float dt = expf(log_dt[d]);
        #pragma unroll
        for (int i = 0; i < 16; i++) {
            const int n0 = half * 32 + 2 * i;
            a2[i] = pack2(expf(dt * (-0.5f * (float)(n0 + 1))),
                          expf(dt * (-0.5f * (float)(n0 + 2))));
            s2[i] = 0ull;
        }
    }

    const float* xg = x + ((size_t)b * LEN + (size_t)ck * TCH) * DMODEL + d0;

    // stage: 64 rows x 64B; lane -> row = lane>>2 (8 rows/pass), 16B quarter
    const int rq = lane >> 2;
    const int cq = (lane & 3) * 4;

    #pragma unroll
    for (int rr = 0; rr < TILE; rr += 8)
        cp_async16(smem_u32(&XS[0][(rr + rq) * K1_DT + cq]),
                   xg + (size_t)(rr + rq) * DMODEL + cq);
    asm volatile("cp.async.commit_group;");

    #pragma unroll 1
    for (int t = 0; t < NTILES; t++) {
        const int buf = t & 1;
        if (t + 1 < NTILES) {
            const float* src = xg + (size_t)(t + 1) * TILE * DMODEL;
            #pragma unroll
            for (int rr = 0; rr < TILE; rr += 8)
                cp_async16(smem_u32(&XS[buf ^ 1][(rr + rq) * K1_DT + cq]),
                           src + (size_t)(rr + rq) * DMODEL + cq);
            asm volatile("cp.async.commit_group;");
            asm volatile("cp.async.wait_group 1;");
        } else {
            asm volatile("cp.async.wait_group 0;");
        }
        __syncwarp();

        const float* xs = &XS[buf][c];
        #pragma unroll 1
        for (int r0 = 0; r0 < TILE; r0 += 8) {
            #pragma unroll
            for (int r = 0; r < 8; r++) {
                const float xv = xs[(r0 + r) * K1_DT];
                const u64   xx = pack2(xv, xv);
                #pragma unroll
                for (int i = 0; i < 16; i++)
                    s2[i] = fma2(a2[i], s2[i], xx);
            }
        }
        __syncwarp();
    }

    u64* Sp = (u64*)(S_scratch + ((((size_t)ck * BATCH + b) * DMODEL + d) * NSTATE + half * 32));
    #pragma unroll
    for (int i = 0; i < 16; i++) Sp[i] = s2[i];
}

// ---------------- K3: lean 8-channel warp-CTA, deferred epilogue ------------
__global__ __launch_bounds__(32)
void s4d_k3_main(const float* __restrict__ x,
                 const float* __restrict__ log_dt,
                 const float* __restrict__ Bm,
                 const float* __restrict__ Cm,
                 const float* __restrict__ Dv,
                 float* __restrict__ y)
{
    __shared__ float XS[2][TILE * K3_DT];   // 4 KB

    const int lane = threadIdx.x;
    const int c    = lane & 7;            // channel within tile
    const int g    = lane >> 3;           // state quarter (0..3)
    const int d0   = blockIdx.x * K3_DT;
    const int d    = d0 + c;
    const int b    = blockIdx.y;
    const int ck   = blockIdx.z;          // 0..3

    // ---- 16 states per lane: n = g*16 + 0..15 (8 packed pairs) ----
    u64 a2[8], cb2[8], s2[8];
    {
        const float dt = expf(log_dt[d]);
        #pragma unroll
        for (int i = 0; i < 8; i++) {
            const int   n0   = g * 16 + 2 * i;
            const float An0  = -0.5f * (float)(n0 + 1);
            const float An1  = -0.5f * (float)(n0 + 2);
            const float dtA0 = dt * An0;
            const float dtA1 = dt * An1;
            a2[i]  = pack2(expf(dtA0), expf(dtA1));
            cb2[i] = pack2(Cm[d * NSTATE + n0]     * Bm[d * NSTATE + n0]     * (expm1f(dtA0) / An0),
                           Cm[d * NSTATE + n0 + 1] * Bm[d * NSTATE + n0 + 1] * (expm1f(dtA1) / An1));

            // carry-in via incremental powers f = a^(T*(ck-1-cp))
            u64 h0 = 0ull;
            if (ck > 0) {
                const u64 w2 = pack2(expf(dtA0 * (float)TCH), expf(dtA1 * (float)TCH));
                u64 f2 = pack2(1.0f, 1.0f);
                #pragma unroll 1
                for (int cp = ck - 1; cp >= 0; cp--) {
                    const u64 sv = *(const u64*)(S_scratch +
                        ((((size_t)cp * BATCH + b) * DMODEL + d) * NSTATE + g * 16 + 2 * i));
                    h0 = fma2(f2, sv, h0);
                    f2 = mul2(f2, w2);
                }
            }
            s2[i] = h0;
        }
    }
    const float Dd = Dv[d];

    const float* xg = x + ((size_t)b * LEN + (size_t)ck * TCH) * DMODEL + d0;
    float*       yb = y + ((size_t)b * LEN + (size_t)ck * TCH) * DMODEL + d;

    // stage: 64 rows x 32B; lane -> row = lane>>1 (16 rows/pass), 16B half
    const int rq = lane >> 1;             // 0..15
    const int cq = (lane & 1) * 4;        // float offset 0 or 4

    #pragma unroll
    for (int rr = 0; rr < TILE; rr += 16)
        cp_async16(smem_u32(&XS[0][(rr + rq) * K3_DT + cq]),
                   xg + (size_t)(rr + rq) * DMODEL + cq);
    asm volatile("cp.async.commit_group;");

    #pragma unroll 1
    for (int t = 0; t < NTILES; t++) {
        const int buf = t & 1;
        if (t + 1 < NTILES) {
            const float* src = xg + (size_t)(t + 1) * TILE * DMODEL;
            #pragma unroll
            for (int rr = 0; rr < TILE; rr += 16)
                cp_async16(smem_u32(&XS[buf ^ 1][(rr + rq) * K3_DT + cq]),
                           src + (size_t)(rr + rq) * DMODEL + cq);
            asm volatile("cp.async.commit_group;");
            asm volatile("cp.async.wait_group 1;");
        } else {
            asm volatile("cp.async.wait_group 0;");
        }
        __syncwarp();

        const float* xs = &XS[buf][c];
        #pragma unroll 1
        for (int r0 = 0; r0 < TILE; r0 += 8) {
            float pacc[8];

            // ---- compute phase: pure FMA, 8 steps of partials ----
            #pragma unroll
            for (int r = 0; r < 8; r++) {
                const float xv = xs[(r0 + r) * K3_DT];   // broadcast across g
                const u64   xx = pack2(xv, xv);
                s2[0] = fma2(a2[0], s2[0], xx);
                s2[1] = fma2(a2[1], s2[1], xx);
                s2[2] = fma2(a2[2], s2[2], xx);
                s2[3] = fma2(a2[3], s2[3], xx);
                s2[4] = fma2(a2[4], s2[4], xx);
                s2[5] = fma2(a2[5], s2[5], xx);
                s2[6] = fma2(a2[6], s2[6], xx);
                s2[7] = fma2(a2[7], s2[7], xx);
                u64 acc0 = mul2(cb2[0], s2[0]);
                u64 acc1 = mul2(cb2[1], s2[1]);
                acc0 = fma2(cb2[2], s2[2], acc0);
                acc1 = fma2(cb2[3], s2[3], acc1);
                acc0 = fma2(cb2[4], s2[4], acc0);
                acc1 = fma2(cb2[5], s2[5], acc1);
                acc0 = fma2(cb2[6], s2[6], acc0);
                acc1 = fma2(cb2[7], s2[7], acc1);
                const u64 acc = add2(acc0, acc1);
                float lo, hi;
                unpack2(acc, lo, hi);
                pacc[r] = lo + hi;
            }

            // ---- shuffle phase: 8 independent chains, pipelined ----
            #pragma unroll
            for (int r = 0; r < 8; r++)
                pacc[r] += __shfl_xor_sync(0xffffffffu, pacc[r], 8);
            #pragma unroll
            for (int r = 0; r < 8; r++)
                pacc[r] += __shfl_xor_sync(0xffffffffu, pacc[r], 16);

            // ---- store burst (g==0 lanes; xv re-read from smem, L1-cheap) ----
            if (g == 0) {
                #pragma unroll
                for (int r = 0; r < 8; r++) {
                    const float xv = xs[(r0 + r) * K3_DT];
                    yb[(size_t)(t * TILE + r0 + r) * DMODEL] = fmaf(Dd, xv, pacc[r]);
                }
            }
        }
        __syncwarp();
    }
}

extern "C" void kernel_launch(void* const* d_in, const int* in_sizes, int n_in,
                              void* d_out, int out_size)
{
    const float* x      = (const float*)d_in[0];  // [8, 2048, 1024]
    const float* log_dt = (const float*)d_in[1];  // [1024]
    const float* Bm     = (const float*)d_in[2];  // [1024, 64]
    const float* Cm     = (const float*)d_in[3];  // [1024, 64]
    const float* Dv     = (const float*)d_in[4];  // [1024]
    float*       y      = (float*)d_out;          // [8, 2048, 1024]

    dim3 block(32);

    dim3 g1(DMODEL / K1_DT, BATCH, NCHUNK - 1);   // (64, 8, 3) = 1536 warp-CTAs
    s4d_k1_states<<<g1, block>>>(x, log_dt);

    dim3 g3(DMODEL / K3_DT, BATCH, NCHUNK);       // (128, 8, 4) = 4096 warp-CTAs
    s4d_k3_main<<<g3, block>>>(x, log_dt, Bm, Cm, Dv, y);
}